// round 13
// baseline (speedup 1.0000x reference)
#include <cuda_runtime.h>
#include <cuda_fp16.h>
#include <mma.h>
#include <math.h>

using namespace nvcuda;

#define N_NODES 50000
#define N_EDGES 1600000
#define NF      128
#define EF      16
#define EFIL    32
#define CLASSES 40
#define CAP     128   // per-node bucket capacity (Poisson(32); P(>128) ~ 1e-35)
#define N2PAD   64    // padded Wg2 column count for wmma
#define OBLD    36    // padded stage-1 output ld (floats): mult of 4, kills 32-way conflicts

// ---------------- device scratch (no allocations allowed) ----------------
__device__ int    g_is64;
__device__ float  g_deg [N_NODES];
__device__ int    g_cnt [N_NODES];
__device__ int2   g_slot[(size_t)N_NODES * CAP];
__device__ __align__(16) __half g_w1h [EF * EFIL];        // fp16 W1
__device__ __align__(16) __half g_wg1h[NF * NF];          // fp16 Wg1
__device__ __align__(16) __half g_wg2h[NF * N2PAD];       // fp16 Wg2, zero-padded
__device__ __align__(16) __half g_h1h [(size_t)N_NODES * NF];       // fp16 x@Wg1
__device__ __align__(16) __half g_r1h [(size_t)N_NODES * NF];       // fp16 relu(out1)
__device__ __align__(16) __half g_h2h [(size_t)N_NODES * CLASSES];  // fp16 relu(out1)@Wg2

// ---------------- k0: deg=1, cnt=0, weight fp16 conversion, dtype detect ----------------
__global__ void k_init_detect(const int* __restrict__ w,
                              const float* __restrict__ W1,
                              const float* __restrict__ Wg1,
                              const float* __restrict__ Wg2) {
    int i = blockIdx.x * blockDim.x + threadIdx.x;
    if (i < N_NODES) { g_deg[i] = 1.0f; g_cnt[i] = 0; }
    if (i < EF * EFIL) g_w1h[i] = __float2half(W1[i]);
    if (i < NF * NF) g_wg1h[i] = __float2half(Wg1[i]);
    if (i < NF * N2PAD) {
        int k = i / N2PAD, n = i % N2PAD;
        g_wg2h[i] = (n < CLASSES) ? __float2half(Wg2[k * CLASSES + n]) : __half(0.0f);
    }
    if (blockIdx.x == 0) {
        __shared__ int any_nonzero;
        if (threadIdx.x == 0) any_nonzero = 0;
        __syncthreads();
        if (w[2 * threadIdx.x + 1] != 0) atomicOr(&any_nonzero, 1);
        __syncthreads();
        if (threadIdx.x == 0) g_is64 = (any_nonzero == 0) ? 1 : 0;
    }
}

// ---------------- k1: fused [tensor gemm1 | tensor edge MLP] by block range ----------------
#define G1_ROWS   64
#define G1_BLOCKS ((N_NODES + G1_ROWS - 1) / G1_ROWS)          // 782
#define MLP_BLOCKS (N_EDGES / 256)                             // 6250 (exact)

__global__ __launch_bounds__(256) void k_mlp_gemm1(
    const float* __restrict__ edge_x,
    const int*   __restrict__ eidx,
    const float* __restrict__ b1, const float* __restrict__ W2,
    const float* __restrict__ b2,
    const float* __restrict__ x)
{
    __shared__ __align__(16) char sbuf[46080];
    int tid = threadIdx.x;

    if (blockIdx.x < G1_BLOCKS) {
        // ---------- gemm1: h1h = fp16(x @ Wg1), tensor cores ----------
        __half* a  = (__half*)sbuf;          // phase 1-2: 64x128 fp16 (16KB)
        float*  ob = (float*)sbuf;           // phase 3:   64x128 fp32 (32KB)
        int base = blockIdx.x * G1_ROWS;
        const float4* xg = (const float4*)(x + (size_t)base * NF);
        int valid4 = (N_NODES - base) * 32;
#pragma unroll
        for (int i = 0; i < (G1_ROWS * 32) / 256; i++) {
            int idx = tid + i * 256;
            float4 v = (idx < valid4) ? xg[idx] : make_float4(0.f, 0.f, 0.f, 0.f);
            half2 p0 = __float22half2_rn(make_float2(v.x, v.y));
            half2 p1 = __float22half2_rn(make_float2(v.z, v.w));
            uint2 u; u.x = *(unsigned*)&p0; u.y = *(unsigned*)&p1;
            ((uint2*)a)[idx] = u;
        }
        __syncthreads();

        int wid = tid >> 5;
        int rt  = wid & 3;
        int nh  = wid >> 2;

        wmma::fragment<wmma::matrix_a, 16, 16, 16, half, wmma::row_major> fa;
        wmma::fragment<wmma::matrix_b, 16, 16, 16, half, wmma::row_major> fb;
        wmma::fragment<wmma::accumulator, 16, 16, 16, float> fc[4];
#pragma unroll
        for (int n = 0; n < 4; n++) wmma::fill_fragment(fc[n], 0.0f);

        for (int k8 = 0; k8 < 8; k8++) {
            wmma::load_matrix_sync(fa, a + rt * 16 * NF + k8 * 16, NF);
#pragma unroll
            for (int n = 0; n < 4; n++) {
                wmma::load_matrix_sync(fb, g_wg1h + k8 * 16 * NF + nh * 64 + n * 16, NF);
                wmma::mma_sync(fc[n], fa, fb, fc[n]);
            }
        }
        __syncthreads();
#pragma unroll
        for (int n = 0; n < 4; n++)
            wmma::store_matrix_sync(ob + rt * 16 * NF + nh * 64 + n * 16, fc[n], NF, wmma::mem_row_major);
        __syncthreads();

        for (int idx = tid; idx < G1_ROWS * 64; idx += 256) {
            int row = idx >> 6;
            int c2  = idx & 63;
            int gr = base + row;
            if (gr < N_NODES) {
                float2 f = ((const float2*)ob)[idx];
                half2 h = __float22half2_rn(f);
                *(half2*)(g_h1h + (size_t)gr * NF + c2 * 2) = h;
            }
        }
    } else {
        // ---------- edge MLP via tensor cores ----------
        __half* A    = (__half*)sbuf;                       // 256x16 fp16 (8KB)
        float*  ob   = (float*)(sbuf + 8192);               // 256x36 fp32 (36864B)
        float*  sW2  = (float*)(sbuf + 8192 + 36864);       // 32
        float*  sb1  = sW2 + 32;                            // 32
        float*  sb2  = sb1 + 32;                            // 1

        int e0 = (blockIdx.x - G1_BLOCKS) * 256;
        int e  = e0 + tid;

        // own-edge load -> fp16 A row
        {
            const float4* ex4 = (const float4*)(edge_x + (size_t)e * EF);
            float4 v0 = ex4[0], v1 = ex4[1], v2 = ex4[2], v3 = ex4[3];
            half2 h0 = __float22half2_rn(make_float2(v0.x, v0.y));
            half2 h1 = __float22half2_rn(make_float2(v0.z, v0.w));
            half2 h2 = __float22half2_rn(make_float2(v1.x, v1.y));
            half2 h3 = __float22half2_rn(make_float2(v1.z, v1.w));
            half2 h4 = __float22half2_rn(make_float2(v2.x, v2.y));
            half2 h5 = __float22half2_rn(make_float2(v2.z, v2.w));
            half2 h6 = __float22half2_rn(make_float2(v3.x, v3.y));
            half2 h7 = __float22half2_rn(make_float2(v3.z, v3.w));
            uint4 u0, u1;
            u0.x = *(unsigned*)&h0; u0.y = *(unsigned*)&h1;
            u0.z = *(unsigned*)&h2; u0.w = *(unsigned*)&h3;
            u1.x = *(unsigned*)&h4; u1.y = *(unsigned*)&h5;
            u1.z = *(unsigned*)&h6; u1.w = *(unsigned*)&h7;
            ((uint4*)(A + tid * EF))[0] = u0;
            ((uint4*)(A + tid * EF))[1] = u1;
        }
        if (tid < 32) { sW2[tid] = W2[tid]; sb1[tid] = b1[tid]; }
        if (tid == 0) *sb2 = b2[0];
        __syncthreads();

        // stage 1: [256x16] @ [16x32], 8 warps x (2 M-tiles x 2 N-tiles)
        {
            int wid = tid >> 5;
            wmma::fragment<wmma::matrix_a, 16, 16, 16, half, wmma::row_major> fa;
            wmma::fragment<wmma::matrix_b, 16, 16, 16, half, wmma::row_major> fb;
            wmma::fragment<wmma::accumulator, 16, 16, 16, float> fc;
#pragma unroll
            for (int i = 0; i < 2; i++) {
                int mt = wid * 2 + i;
                wmma::load_matrix_sync(fa, A + mt * 16 * EF, EF);
#pragma unroll
                for (int nt = 0; nt < 2; nt++) {
                    wmma::fill_fragment(fc, 0.0f);
                    wmma::load_matrix_sync(fb, g_w1h + nt * 16, EFIL);
                    wmma::mma_sync(fc, fa, fb, fc);
                    wmma::store_matrix_sync(ob + mt * 16 * OBLD + nt * 16, fc, OBLD, wmma::mem_row_major);
                }
            }
        }
        __syncthreads();

        // stage 2: relu(h + b1) . W2 + b2 -> sigmoid
        float acc = *sb2;
        const float4* row = (const float4*)(ob + tid * OBLD);
#pragma unroll
        for (int j = 0; j < 8; j++) {
            float4 v = row[j];
            acc = fmaf(fmaxf(v.x + sb1[j*4+0], 0.f), sW2[j*4+0], acc);
            acc = fmaf(fmaxf(v.y + sb1[j*4+1], 0.f), sW2[j*4+1], acc);
            acc = fmaf(fmaxf(v.z + sb1[j*4+2], 0.f), sW2[j*4+2], acc);
            acc = fmaf(fmaxf(v.w + sb1[j*4+3], 0.f), sW2[j*4+3], acc);
        }
        float w = 1.0f / (1.0f + __expf(-acc));

        int r, c;
        if (g_is64) {
            r = eidx[2 * (size_t)e];
            c = eidx[2 * ((size_t)N_EDGES + e)];
        } else {
            r = eidx[e];
            c = eidx[N_EDGES + e];
        }
        r = min(max(r, 0), N_NODES - 1);
        c = min(max(c, 0), N_NODES - 1);

        int pos = atomicAdd(&g_cnt[c], 1);
        if (pos < CAP) g_slot[(size_t)c * CAP + pos] = make_int2(r, __float_as_int(w));
        atomicAdd(&g_deg[c], w);
    }
}

// ---------------- k4: gather conv1 — warp/node, inline rsqrt, unrolled fast path ----------------
__global__ __launch_bounds__(256) void k_gather1(const float* __restrict__ bg1) {
    int c    = (blockIdx.x * blockDim.x + threadIdx.x) >> 5;
    int lane = threadIdx.x & 31;
    if (c >= N_NODES) return;

    int   cnt = min(g_cnt[c], CAP);
    float dc  = rsqrtf(g_deg[c]);
    float dd  = dc * dc;

    int half_ = lane >> 4;
    int hl    = lane & 15;

    float acc[8];
#pragma unroll
    for (int k = 0; k < 8; k++) acc[k] = 0.f;

    int2* sl = g_slot + (size_t)c * CAP;
    int base = 0;
    for (; base + 32 <= cnt; base += 32) {           // fast path: full 32 slots
        int2 p = sl[base + lane];
        int   src = p.x;
        float nrm = rsqrtf(g_deg[src]) * __int_as_float(p.y) * dc;
        sl[base + lane].y = __float_as_int(nrm);     // store for conv2
#pragma unroll
        for (int j = 0; j < 32; j += 2) {
            int jj = j + half_;
            int   s = __shfl_sync(0xFFFFFFFFu, src, jj);
            float n = __shfl_sync(0xFFFFFFFFu, nrm, jj);
            uint4 v = __ldg(&((const uint4*)(g_h1h + (size_t)s * NF))[hl]);
            half2* hp = (half2*)&v;
#pragma unroll
            for (int k = 0; k < 4; k++) {
                float2 f = __half22float2(hp[k]);
                acc[2*k]   = fmaf(f.x, n, acc[2*k]);
                acc[2*k+1] = fmaf(f.y, n, acc[2*k+1]);
            }
        }
    }
    if (base < cnt) {                                // tail
        int   src = 0;
        float nrm = 0.0f;
        if (base + lane < cnt) {
            int2 p = sl[base + lane];
            src = p.x;
            nrm = rsqrtf(g_deg[src]) * __int_as_float(p.y) * dc;
            sl[base + lane].y = __float_as_int(nrm);
        }
        int m = cnt - base;
        for (int j = 0; j < m; j += 2) {
            int jj = j + half_;
            int   s = __shfl_sync(0xFFFFFFFFu, src, jj & 31);
            float n = __shfl_sync(0xFFFFFFFFu, nrm, jj & 31);
            if (jj < m) {
                uint4 v = __ldg(&((const uint4*)(g_h1h + (size_t)s * NF))[hl]);
                half2* hp = (half2*)&v;
#pragma unroll
                for (int k = 0; k < 4; k++) {
                    float2 f = __half22float2(hp[k]);
                    acc[2*k]   = fmaf(f.x, n, acc[2*k]);
                    acc[2*k+1] = fmaf(f.y, n, acc[2*k+1]);
                }
            }
        }
    }
#pragma unroll
    for (int k = 0; k < 8; k++)
        acc[k] += __shfl_xor_sync(0xFFFFFFFFu, acc[k], 16);

    if (half_ == 0) {
        uint4 v = ((const uint4*)(g_h1h + (size_t)c * NF))[hl];
        half2* hp = (half2*)&v;
        const float4* bv = (const float4*)(bg1 + hl * 8);
        float4 b0 = __ldg(&bv[0]);
        float4 b1 = __ldg(&bv[1]);
        float bb[8] = {b0.x, b0.y, b0.z, b0.w, b1.x, b1.y, b1.z, b1.w};
        half2 o[4];
#pragma unroll
        for (int k = 0; k < 4; k++) {
            float2 f = __half22float2(hp[k]);
            float v0 = fmaxf(fmaf(f.x, dd, acc[2*k])   + bb[2*k],   0.0f);
            float v1 = fmaxf(fmaf(f.y, dd, acc[2*k+1]) + bb[2*k+1], 0.0f);
            o[k] = __float22half2_rn(make_float2(v0, v1));
        }
        uint4 u;
        u.x = *(unsigned*)&o[0]; u.y = *(unsigned*)&o[1];
        u.z = *(unsigned*)&o[2]; u.w = *(unsigned*)&o[3];
        ((uint4*)(g_r1h + (size_t)c * NF))[hl] = u;
    }
}

// ---------------- k5: gemm2 tensor: h2h = fp16(r1h @ Wg2h) ----------------
__global__ __launch_bounds__(192) void k_gemm2() {
    __shared__ __align__(16) __half a2[G1_ROWS * NF];
    __shared__ __align__(16) float  ob[G1_ROWS * 48];
    int base = blockIdx.x * G1_ROWS;
    int tid  = threadIdx.x;

    const uint4* rg = (const uint4*)(g_r1h + (size_t)base * NF);
    int valid8 = (N_NODES - base) * 16;
    for (int i = tid; i < G1_ROWS * 16; i += 192) {
        uint4 v = (i < valid8) ? rg[i] : make_uint4(0, 0, 0, 0);
        ((uint4*)a2)[i] = v;
    }
    __syncthreads();

    int wid = tid >> 5;
    wmma::fragment<wmma::matrix_a, 16, 16, 16, half, wmma::row_major> fa;
    wmma::fragment<wmma::matrix_b, 16, 16, 16, half, wmma::row_major> fb;
    wmma::fragment<wmma::accumulator, 16, 16, 16, float> fc;

#pragma unroll
    for (int i = 0; i < 2; i++) {
        int t  = wid * 2 + i;
        int rt = t / 3, ct = t % 3;
        wmma::fill_fragment(fc, 0.0f);
        for (int k8 = 0; k8 < 8; k8++) {
            wmma::load_matrix_sync(fa, a2 + rt * 16 * NF + k8 * 16, NF);
            wmma::load_matrix_sync(fb, g_wg2h + k8 * 16 * N2PAD + ct * 16, N2PAD);
            wmma::mma_sync(fc, fa, fb, fc);
        }
        wmma::store_matrix_sync(ob + rt * 16 * 48 + ct * 16, fc, 48, wmma::mem_row_major);
    }
    __syncthreads();

    for (int idx = tid; idx < G1_ROWS * 20; idx += 192) {
        int row = idx / 20;
        int c2  = idx % 20;
        int gr  = base + row;
        if (gr < N_NODES) {
            float2 f = make_float2(ob[row * 48 + c2 * 2], ob[row * 48 + c2 * 2 + 1]);
            *(half2*)(g_h2h + (size_t)gr * CLASSES + c2 * 2) = __float22half2_rn(f);
        }
    }
}

// ---------------- k6: gather conv2 — warp/node, 3 slots in flight, unrolled fast path ----------------
__global__ __launch_bounds__(256) void k_gather2(
    const float* __restrict__ bg2, float* __restrict__ out2)
{
    int c    = (blockIdx.x * blockDim.x + threadIdx.x) >> 5;
    int lane = threadIdx.x & 31;
    if (c >= N_NODES) return;

    int   cnt = min(g_cnt[c], CAP);
    float dd  = 1.0f / g_deg[c];

    int sub = lane / 10;
    int q   = lane - sub * 10;
    bool act = (lane < 30);

    float acc[4] = {0.f, 0.f, 0.f, 0.f};

    const int2* sl = g_slot + (size_t)c * CAP;
    int base = 0;
    for (; base + 32 <= cnt; base += 32) {           // fast path
        int2 p = sl[base + lane];
        int   src = p.x;
        float nrm = __int_as_float(p.y);
#pragma unroll
        for (int j = 0; j < 32; j += 3) {
            int jj = j + sub;
            int   s = __shfl_sync(0xFFFFFFFFu, src, jj & 31);
            float n = __shfl_sync(0xFFFFFFFFu, nrm, jj & 31);
            if (act && jj < 32) {
                uint2 v = __ldg((const uint2*)(g_h2h + (size_t)s * CLASSES) + q);
                half2* hp = (half2*)&v;
                float2 f0 = __half22float2(hp[0]);
                float2 f1 = __half22float2(hp[1]);
                acc[0] = fmaf(f0.x, n, acc[0]);
                acc[1] = fmaf(f0.y, n, acc[1]);
                acc[2] = fmaf(f1.x, n, acc[2]);
                acc[3] = fmaf(f1.y, n, acc[3]);
            }
        }
    }
    if (base < cnt) {                                // tail
        int   src = 0;
        float nrm = 0.0f;
        if (base + lane < cnt) {
            int2 p = sl[base + lane];
            src = p.x;
            nrm = __int_as_float(p.y);
        }
        int m = cnt - base;
        for (int j = 0; j < m; j += 3) {
            int jj = j + sub;
            int   s = __shfl_sync(0xFFFFFFFFu, src, jj & 31);
            float n = __shfl_sync(0xFFFFFFFFu, nrm, jj & 31);
            if (act && jj < m) {
                uint2 v = __ldg((const uint2*)(g_h2h + (size_t)s * CLASSES) + q);
                half2* hp = (half2*)&v;
                float2 f0 = __half22float2(hp[0]);
                float2 f1 = __half22float2(hp[1]);
                acc[0] = fmaf(f0.x, n, acc[0]);
                acc[1] = fmaf(f0.y, n, acc[1]);
                acc[2] = fmaf(f1.x, n, acc[2]);
                acc[3] = fmaf(f1.y, n, acc[3]);
            }
        }
    }
#pragma unroll
    for (int k = 0; k < 4; k++) {
        float v1 = __shfl_down_sync(0xFFFFFFFFu, acc[k], 10);
        float v2 = __shfl_down_sync(0xFFFFFFFFu, acc[k], 20);
        acc[k] += v1 + v2;
    }

    if (lane < 10) {
        uint2 v = ((const uint2*)(g_h2h + (size_t)c * CLASSES))[lane];
        half2* hp = (half2*)&v;
        float2 f0 = __half22float2(hp[0]);
        float2 f1 = __half22float2(hp[1]);
        float4 b = __ldg(&((const float4*)bg2)[lane]);
        float4 o;
        o.x = fmaf(f0.x, dd, acc[0]) + b.x;
        o.y = fmaf(f0.y, dd, acc[1]) + b.y;
        o.z = fmaf(f1.x, dd, acc[2]) + b.z;
        o.w = fmaf(f1.y, dd, acc[3]) + b.w;
        ((float4*)(out2 + (size_t)c * CLASSES))[lane] = o;
    }
}

// ---------------- launch ----------------
extern "C" void kernel_launch(void* const* d_in, const int* in_sizes, int n_in,
                              void* d_out, int out_size)
{
    const float* x      = (const float*)d_in[0];
    const int*   eidx   = (const int*)d_in[1];
    const float* edge_x = (const float*)d_in[2];
    const float* W1     = (const float*)d_in[3];
    const float* b1     = (const float*)d_in[4];
    const float* W2     = (const float*)d_in[5];
    const float* b2     = (const float*)d_in[6];
    const float* Wg1    = (const float*)d_in[7];
    const float* bg1    = (const float*)d_in[8];
    const float* Wg2    = (const float*)d_in[9];
    const float* bg2    = (const float*)d_in[10];
    float*       out2   = (float*)d_out;

    k_init_detect<<<(N_NODES + 255) / 256, 256>>>(eidx, W1, Wg1, Wg2);
    k_mlp_gemm1<<<G1_BLOCKS + MLP_BLOCKS, 256>>>(edge_x, eidx, b1, W2, b2, x);
    k_gather1<<<(N_NODES * 32 + 255) / 256, 256>>>(bg1);
    k_gemm2<<<(N_NODES + G1_ROWS - 1) / G1_ROWS, 192>>>();
    k_gather2<<<(N_NODES * 32 + 255) / 256, 256>>>(bg2, out2);
}

// round 14
// speedup vs baseline: 1.0639x; 1.0639x over previous
#include <cuda_runtime.h>
#include <cuda_fp16.h>
#include <mma.h>
#include <math.h>

using namespace nvcuda;

#define N_NODES 50000
#define N_EDGES 1600000
#define NF      128
#define EF      16
#define EFIL    32
#define CLASSES 40
#define CAP     128   // per-node bucket capacity (Poisson(32); P(>128) ~ 1e-35)
#define N2PAD   64    // padded Wg2 column count for wmma
#define OBLD    36    // edge-MLP stage-1 output ld (floats)
#define ALD     136   // gemm1 smem A ld (halves) — breaks bank aliasing
#define OLD1    132   // gemm1 smem fp32 staging ld (floats)
#define G2R     128   // gemm2 rows per block
#define G2_BLOCKS ((N_NODES + G2R - 1) / G2R)   // 391
#define N_PADROWS (G2_BLOCKS * G2R)             // 50048 (padded rows stay zero)
#define OLD2    52    // gemm2 smem fp32 staging ld (floats)

// ---------------- device scratch (no allocations allowed) ----------------
__device__ int    g_is64;
__device__ float  g_deg [N_NODES];
__device__ int    g_cnt [N_NODES];
__device__ int2   g_slot[(size_t)N_NODES * CAP];
__device__ __align__(16) __half g_w1h [EF * EFIL];
__device__ __align__(16) __half g_wg1h[NF * NF];
__device__ __align__(16) __half g_wg2h[NF * N2PAD];
__device__ __align__(16) __half g_h1h [(size_t)N_NODES * NF];
__device__ __align__(16) __half g_r1h [(size_t)N_PADROWS * NF];     // padded for gemm2 tiles
__device__ __align__(16) __half g_h2h [(size_t)N_NODES * CLASSES];

// ---------------- k0: deg=1, cnt=0, weight fp16 conversion, dtype detect ----------------
__global__ void k_init_detect(const int* __restrict__ w,
                              const float* __restrict__ W1,
                              const float* __restrict__ Wg1,
                              const float* __restrict__ Wg2) {
    int i = blockIdx.x * blockDim.x + threadIdx.x;
    if (i < N_NODES) { g_deg[i] = 1.0f; g_cnt[i] = 0; }
    if (i < EF * EFIL) g_w1h[i] = __float2half(W1[i]);
    if (i < NF * NF) g_wg1h[i] = __float2half(Wg1[i]);
    if (i < NF * N2PAD) {
        int k = i / N2PAD, n = i % N2PAD;
        g_wg2h[i] = (n < CLASSES) ? __float2half(Wg2[k * CLASSES + n]) : __half(0.0f);
    }
    if (blockIdx.x == 0) {
        __shared__ int any_nonzero;
        if (threadIdx.x == 0) any_nonzero = 0;
        __syncthreads();
        if (w[2 * threadIdx.x + 1] != 0) atomicOr(&any_nonzero, 1);
        __syncthreads();
        if (threadIdx.x == 0) g_is64 = (any_nonzero == 0) ? 1 : 0;
    }
}

// ---------------- k1: fused [tensor gemm1 | tensor edge MLP] by block range ----------------
#define G1_ROWS   64
#define G1_BLOCKS ((N_NODES + G1_ROWS - 1) / G1_ROWS)          // 782
#define MLP_BLOCKS (N_EDGES / 256)                             // 6250 (exact)

__global__ __launch_bounds__(256) void k_mlp_gemm1(
    const float* __restrict__ edge_x,
    const int*   __restrict__ eidx,
    const float* __restrict__ b1, const float* __restrict__ W2,
    const float* __restrict__ b2,
    const float* __restrict__ x)
{
    __shared__ __align__(16) char sbuf[46080];
    int tid = threadIdx.x;

    if (blockIdx.x < G1_BLOCKS) {
        // ---------- gemm1: h1h = fp16(x @ Wg1), tensor cores, padded smem ----------
        __half* a  = (__half*)sbuf;          // 64 x ALD fp16 (17408B), phase 1-2
        float*  ob = (float*)sbuf;           // 64 x OLD1 fp32 (33792B), phase 3
        int base = blockIdx.x * G1_ROWS;
        const float4* xg = (const float4*)(x + (size_t)base * NF);
        int valid4 = (N_NODES - base) * 32;
#pragma unroll
        for (int i = 0; i < (G1_ROWS * 32) / 256; i++) {
            int idx = tid + i * 256;
            int row = idx >> 5, col = idx & 31;
            float4 v = (idx < valid4) ? xg[idx] : make_float4(0.f, 0.f, 0.f, 0.f);
            half2 p0 = __float22half2_rn(make_float2(v.x, v.y));
            half2 p1 = __float22half2_rn(make_float2(v.z, v.w));
            uint2 u; u.x = *(unsigned*)&p0; u.y = *(unsigned*)&p1;
            ((uint2*)(a + row * ALD))[col] = u;
        }
        __syncthreads();

        int wid = tid >> 5;
        int rt  = wid & 3;
        int nh  = wid >> 2;

        wmma::fragment<wmma::matrix_a, 16, 16, 16, half, wmma::row_major> fa;
        wmma::fragment<wmma::matrix_b, 16, 16, 16, half, wmma::row_major> fb;
        wmma::fragment<wmma::accumulator, 16, 16, 16, float> fc[4];
#pragma unroll
        for (int n = 0; n < 4; n++) wmma::fill_fragment(fc[n], 0.0f);

        for (int k8 = 0; k8 < 8; k8++) {
            wmma::load_matrix_sync(fa, a + rt * 16 * ALD + k8 * 16, ALD);
#pragma unroll
            for (int n = 0; n < 4; n++) {
                wmma::load_matrix_sync(fb, g_wg1h + k8 * 16 * NF + nh * 64 + n * 16, NF);
                wmma::mma_sync(fc[n], fa, fb, fc[n]);
            }
        }
        __syncthreads();
#pragma unroll
        for (int n = 0; n < 4; n++)
            wmma::store_matrix_sync(ob + rt * 16 * OLD1 + nh * 64 + n * 16, fc[n], OLD1, wmma::mem_row_major);
        __syncthreads();

        for (int idx = tid; idx < G1_ROWS * 64; idx += 256) {
            int row = idx >> 6;
            int c2  = idx & 63;
            int gr = base + row;
            if (gr < N_NODES) {
                float2 f = *(const float2*)(ob + row * OLD1 + c2 * 2);
                half2 h = __float22half2_rn(f);
                *(half2*)(g_h1h + (size_t)gr * NF + c2 * 2) = h;
            }
        }
    } else {
        // ---------- edge MLP via tensor cores ----------
        __half* A    = (__half*)sbuf;                       // 256x16 fp16 (8KB)
        float*  ob   = (float*)(sbuf + 8192);               // 256xOBLD fp32 (36864B)
        float*  sW2  = (float*)(sbuf + 8192 + 36864);       // 32
        float*  sb1  = sW2 + 32;                            // 32
        float*  sb2  = sb1 + 32;                            // 1

        int e0 = (blockIdx.x - G1_BLOCKS) * 256;
        int e  = e0 + tid;

        {
            const float4* ex4 = (const float4*)(edge_x + (size_t)e * EF);
            float4 v0 = ex4[0], v1 = ex4[1], v2 = ex4[2], v3 = ex4[3];
            half2 h0 = __float22half2_rn(make_float2(v0.x, v0.y));
            half2 h1 = __float22half2_rn(make_float2(v0.z, v0.w));
            half2 h2 = __float22half2_rn(make_float2(v1.x, v1.y));
            half2 h3 = __float22half2_rn(make_float2(v1.z, v1.w));
            half2 h4 = __float22half2_rn(make_float2(v2.x, v2.y));
            half2 h5 = __float22half2_rn(make_float2(v2.z, v2.w));
            half2 h6 = __float22half2_rn(make_float2(v3.x, v3.y));
            half2 h7 = __float22half2_rn(make_float2(v3.z, v3.w));
            uint4 u0, u1;
            u0.x = *(unsigned*)&h0; u0.y = *(unsigned*)&h1;
            u0.z = *(unsigned*)&h2; u0.w = *(unsigned*)&h3;
            u1.x = *(unsigned*)&h4; u1.y = *(unsigned*)&h5;
            u1.z = *(unsigned*)&h6; u1.w = *(unsigned*)&h7;
            ((uint4*)(A + tid * EF))[0] = u0;
            ((uint4*)(A + tid * EF))[1] = u1;
        }
        if (tid < 32) { sW2[tid] = W2[tid]; sb1[tid] = b1[tid]; }
        if (tid == 0) *sb2 = b2[0];
        __syncthreads();

        {
            int wid = tid >> 5;
            wmma::fragment<wmma::matrix_a, 16, 16, 16, half, wmma::row_major> fa;
            wmma::fragment<wmma::matrix_b, 16, 16, 16, half, wmma::row_major> fb;
            wmma::fragment<wmma::accumulator, 16, 16, 16, float> fc;
#pragma unroll
            for (int i = 0; i < 2; i++) {
                int mt = wid * 2 + i;
                wmma::load_matrix_sync(fa, A + mt * 16 * EF, EF);
#pragma unroll
                for (int nt = 0; nt < 2; nt++) {
                    wmma::fill_fragment(fc, 0.0f);
                    wmma::load_matrix_sync(fb, g_w1h + nt * 16, EFIL);
                    wmma::mma_sync(fc, fa, fb, fc);
                    wmma::store_matrix_sync(ob + mt * 16 * OBLD + nt * 16, fc, OBLD, wmma::mem_row_major);
                }
            }
        }
        __syncthreads();

        float acc = *sb2;
        const float4* row = (const float4*)(ob + tid * OBLD);
#pragma unroll
        for (int j = 0; j < 8; j++) {
            float4 v = row[j];
            acc = fmaf(fmaxf(v.x + sb1[j*4+0], 0.f), sW2[j*4+0], acc);
            acc = fmaf(fmaxf(v.y + sb1[j*4+1], 0.f), sW2[j*4+1], acc);
            acc = fmaf(fmaxf(v.z + sb1[j*4+2], 0.f), sW2[j*4+2], acc);
            acc = fmaf(fmaxf(v.w + sb1[j*4+3], 0.f), sW2[j*4+3], acc);
        }
        float w = 1.0f / (1.0f + __expf(-acc));

        int r, c;
        if (g_is64) {
            r = eidx[2 * (size_t)e];
            c = eidx[2 * ((size_t)N_EDGES + e)];
        } else {
            r = eidx[e];
            c = eidx[N_EDGES + e];
        }
        r = min(max(r, 0), N_NODES - 1);
        c = min(max(c, 0), N_NODES - 1);

        int pos = atomicAdd(&g_cnt[c], 1);
        if (pos < CAP) g_slot[(size_t)c * CAP + pos] = make_int2(r, __float_as_int(w));
        atomicAdd(&g_deg[c], w);
    }
}

// ---------------- k4: gather conv1 — warp/node, inline rsqrt, unrolled fast path ----------------
__global__ __launch_bounds__(256) void k_gather1(const float* __restrict__ bg1) {
    int c    = (blockIdx.x * blockDim.x + threadIdx.x) >> 5;
    int lane = threadIdx.x & 31;
    if (c >= N_NODES) return;

    int   cnt = min(g_cnt[c], CAP);
    float dc  = rsqrtf(g_deg[c]);
    float dd  = dc * dc;

    int half_ = lane >> 4;
    int hl    = lane & 15;

    float acc[8];
#pragma unroll
    for (int k = 0; k < 8; k++) acc[k] = 0.f;

    int2* sl = g_slot + (size_t)c * CAP;
    int base = 0;
    for (; base + 32 <= cnt; base += 32) {
        int2 p = sl[base + lane];
        int   src = p.x;
        float nrm = rsqrtf(g_deg[src]) * __int_as_float(p.y) * dc;
        sl[base + lane].y = __float_as_int(nrm);
#pragma unroll
        for (int j = 0; j < 32; j += 2) {
            int jj = j + half_;
            int   s = __shfl_sync(0xFFFFFFFFu, src, jj);
            float n = __shfl_sync(0xFFFFFFFFu, nrm, jj);
            uint4 v = __ldg(&((const uint4*)(g_h1h + (size_t)s * NF))[hl]);
            half2* hp = (half2*)&v;
#pragma unroll
            for (int k = 0; k < 4; k++) {
                float2 f = __half22float2(hp[k]);
                acc[2*k]   = fmaf(f.x, n, acc[2*k]);
                acc[2*k+1] = fmaf(f.y, n, acc[2*k+1]);
            }
        }
    }
    if (base < cnt) {
        int   src = 0;
        float nrm = 0.0f;
        if (base + lane < cnt) {
            int2 p = sl[base + lane];
            src = p.x;
            nrm = rsqrtf(g_deg[src]) * __int_as_float(p.y) * dc;
            sl[base + lane].y = __float_as_int(nrm);
        }
        int m = cnt - base;
        for (int j = 0; j < m; j += 2) {
            int jj = j + half_;
            int   s = __shfl_sync(0xFFFFFFFFu, src, jj & 31);
            float n = __shfl_sync(0xFFFFFFFFu, nrm, jj & 31);
            if (jj < m) {
                uint4 v = __ldg(&((const uint4*)(g_h1h + (size_t)s * NF))[hl]);
                half2* hp = (half2*)&v;
#pragma unroll
                for (int k = 0; k < 4; k++) {
                    float2 f = __half22float2(hp[k]);
                    acc[2*k]   = fmaf(f.x, n, acc[2*k]);
                    acc[2*k+1] = fmaf(f.y, n, acc[2*k+1]);
                }
            }
        }
    }
#pragma unroll
    for (int k = 0; k < 8; k++)
        acc[k] += __shfl_xor_sync(0xFFFFFFFFu, acc[k], 16);

    if (half_ == 0) {
        uint4 v = ((const uint4*)(g_h1h + (size_t)c * NF))[hl];
        half2* hp = (half2*)&v;
        const float4* bv = (const float4*)(bg1 + hl * 8);
        float4 b0 = __ldg(&bv[0]);
        float4 b1 = __ldg(&bv[1]);
        float bb[8] = {b0.x, b0.y, b0.z, b0.w, b1.x, b1.y, b1.z, b1.w};
        half2 o[4];
#pragma unroll
        for (int k = 0; k < 4; k++) {
            float2 f = __half22float2(hp[k]);
            float v0 = fmaxf(fmaf(f.x, dd, acc[2*k])   + bb[2*k],   0.0f);
            float v1 = fmaxf(fmaf(f.y, dd, acc[2*k+1]) + bb[2*k+1], 0.0f);
            o[k] = __float22half2_rn(make_float2(v0, v1));
        }
        uint4 u;
        u.x = *(unsigned*)&o[0]; u.y = *(unsigned*)&o[1];
        u.z = *(unsigned*)&o[2]; u.w = *(unsigned*)&o[3];
        ((uint4*)(g_r1h + (size_t)c * NF))[hl] = u;
    }
}

// ---------------- k5: gemm2 — wmma A direct from global, 128 rows/block ----------------
__global__ __launch_bounds__(256) void k_gemm2() {
    __shared__ __align__(16) float ob[G2R * OLD2];        // 26624B
    int base = blockIdx.x * G2R;
    int tid  = threadIdx.x;
    int wid  = tid >> 5;                                  // 0..7 = row tile

    wmma::fragment<wmma::matrix_a, 16, 16, 16, half, wmma::row_major> fa;
    wmma::fragment<wmma::matrix_b, 16, 16, 16, half, wmma::row_major> fb;
    wmma::fragment<wmma::accumulator, 16, 16, 16, float> fc[3];
#pragma unroll
    for (int n = 0; n < 3; n++) wmma::fill_fragment(fc[n], 0.0f);

    const __half* arow = g_r1h + (size_t)(base + wid * 16) * NF;   // padded: always in-bounds
    for (int k8 = 0; k8 < 8; k8++) {
        wmma::load_matrix_sync(fa, arow + k8 * 16, NF);
#pragma unroll
        for (int ct = 0; ct < 3; ct++) {
            wmma::load_matrix_sync(fb, g_wg2h + k8 * 16 * N2PAD + ct * 16, N2PAD);
            wmma::mma_sync(fc[ct], fa, fb, fc[ct]);
        }
    }
#pragma unroll
    for (int ct = 0; ct < 3; ct++)
        wmma::store_matrix_sync(ob + wid * 16 * OLD2 + ct * 16, fc[ct], OLD2, wmma::mem_row_major);
    __syncthreads();

    for (int idx = tid; idx < G2R * 20; idx += 256) {     // half2 units
        int row = idx / 20;
        int c2  = idx % 20;
        int gr  = base + row;
        if (gr < N_NODES) {
            float2 f = *(const float2*)(ob + row * OLD2 + c2 * 2);
            *(half2*)(g_h2h + (size_t)gr * CLASSES + c2 * 2) = __float22half2_rn(f);
        }
    }
}

// ---------------- k6: gather conv2 — warp/node, 3 slots in flight, unrolled fast path ----------------
__global__ __launch_bounds__(256) void k_gather2(
    const float* __restrict__ bg2, float* __restrict__ out2)
{
    int c    = (blockIdx.x * blockDim.x + threadIdx.x) >> 5;
    int lane = threadIdx.x & 31;
    if (c >= N_NODES) return;

    int   cnt = min(g_cnt[c], CAP);
    float dd  = 1.0f / g_deg[c];

    int sub = lane / 10;
    int q   = lane - sub * 10;
    bool act = (lane < 30);

    float acc[4] = {0.f, 0.f, 0.f, 0.f};

    const int2* sl = g_slot + (size_t)c * CAP;
    int base = 0;
    for (; base + 32 <= cnt; base += 32) {
        int2 p = sl[base + lane];
        int   src = p.x;
        float nrm = __int_as_float(p.y);
#pragma unroll
        for (int j = 0; j < 32; j += 3) {
            int jj = j + sub;
            int   s = __shfl_sync(0xFFFFFFFFu, src, jj & 31);
            float n = __shfl_sync(0xFFFFFFFFu, nrm, jj & 31);
            if (act && jj < 32) {
                uint2 v = __ldg((const uint2*)(g_h2h + (size_t)s * CLASSES) + q);
                half2* hp = (half2*)&v;
                float2 f0 = __half22float2(hp[0]);
                float2 f1 = __half22float2(hp[1]);
                acc[0] = fmaf(f0.x, n, acc[0]);
                acc[1] = fmaf(f0.y, n, acc[1]);
                acc[2] = fmaf(f1.x, n, acc[2]);
                acc[3] = fmaf(f1.y, n, acc[3]);
            }
        }
    }
    if (base < cnt) {
        int   src = 0;
        float nrm = 0.0f;
        if (base + lane < cnt) {
            int2 p = sl[base + lane];
            src = p.x;
            nrm = __int_as_float(p.y);
        }
        int m = cnt - base;
        for (int j = 0; j < m; j += 3) {
            int jj = j + sub;
            int   s = __shfl_sync(0xFFFFFFFFu, src, jj & 31);
            float n = __shfl_sync(0xFFFFFFFFu, nrm, jj & 31);
            if (act && jj < m) {
                uint2 v = __ldg((const uint2*)(g_h2h + (size_t)s * CLASSES) + q);
                half2* hp = (half2*)&v;
                float2 f0 = __half22float2(hp[0]);
                float2 f1 = __half22float2(hp[1]);
                acc[0] = fmaf(f0.x, n, acc[0]);
                acc[1] = fmaf(f0.y, n, acc[1]);
                acc[2] = fmaf(f1.x, n, acc[2]);
                acc[3] = fmaf(f1.y, n, acc[3]);
            }
        }
    }
#pragma unroll
    for (int k = 0; k < 4; k++) {
        float v1 = __shfl_down_sync(0xFFFFFFFFu, acc[k], 10);
        float v2 = __shfl_down_sync(0xFFFFFFFFu, acc[k], 20);
        acc[k] += v1 + v2;
    }

    if (lane < 10) {
        uint2 v = ((const uint2*)(g_h2h + (size_t)c * CLASSES))[lane];
        half2* hp = (half2*)&v;
        float2 f0 = __half22float2(hp[0]);
        float2 f1 = __half22float2(hp[1]);
        float4 b = __ldg(&((const float4*)bg2)[lane]);
        float4 o;
        o.x = fmaf(f0.x, dd, acc[0]) + b.x;
        o.y = fmaf(f0.y, dd, acc[1]) + b.y;
        o.z = fmaf(f1.x, dd, acc[2]) + b.z;
        o.w = fmaf(f1.y, dd, acc[3]) + b.w;
        ((float4*)(out2 + (size_t)c * CLASSES))[lane] = o;
    }
}

// ---------------- launch ----------------
extern "C" void kernel_launch(void* const* d_in, const int* in_sizes, int n_in,
                              void* d_out, int out_size)
{
    const float* x      = (const float*)d_in[0];
    const int*   eidx   = (const int*)d_in[1];
    const float* edge_x = (const float*)d_in[2];
    const float* W1     = (const float*)d_in[3];
    const float* b1     = (const float*)d_in[4];
    const float* W2     = (const float*)d_in[5];
    const float* b2     = (const float*)d_in[6];
    const float* Wg1    = (const float*)d_in[7];
    const float* bg1    = (const float*)d_in[8];
    const float* Wg2    = (const float*)d_in[9];
    const float* bg2    = (const float*)d_in[10];
    float*       out2   = (float*)d_out;

    k_init_detect<<<(N_NODES + 255) / 256, 256>>>(eidx, W1, Wg1, Wg2);
    k_mlp_gemm1<<<G1_BLOCKS + MLP_BLOCKS, 256>>>(edge_x, eidx, b1, W2, b2, x);
    k_gather1<<<(N_NODES * 32 + 255) / 256, 256>>>(bg1);
    k_gemm2<<<G2_BLOCKS, 256>>>();
    k_gather2<<<(N_NODES * 32 + 255) / 256, 256>>>(bg2, out2);
}